// round 14
// baseline (speedup 1.0000x reference)
#include <cuda_runtime.h>
#include <cuda_fp16.h>
#include <cstdint>

#define MAXN 50000
#define MAXE 800000

// Device scratch (allocation-free rule: __device__ globals)
__device__ float g_diag[(size_t)MAXN * 16];   // per-node Gram accumulators
__device__ float g_invs[(size_t)MAXN * 16];   // per-node inverse sqrt matrices
__device__ uint2 g_triu[(size_t)MAXE * 4];    // per-edge M1^T M2, fp16-packed rows

// float4 helpers
__device__ __forceinline__ float4 f4_fma(float s, float4 v, float4 acc) {
    acc.x = fmaf(s, v.x, acc.x); acc.y = fmaf(s, v.y, acc.y);
    acc.z = fmaf(s, v.z, acc.z); acc.w = fmaf(s, v.w, acc.w);
    return acc;
}
__device__ __forceinline__ float pick(float4 v, int a) {
    float r = v.x;
    r = (a == 1) ? v.y : r;
    r = (a == 2) ? v.z : r;
    r = (a == 3) ? v.w : r;
    return r;
}
__device__ __forceinline__ float4 shfl4(float4 v, int src) {
    float4 r;
    r.x = __shfl_sync(0xffffffffu, v.x, src, 4);
    r.y = __shfl_sync(0xffffffffu, v.y, src, 4);
    r.z = __shfl_sync(0xffffffffu, v.z, src, 4);
    r.w = __shfl_sync(0xffffffffu, v.w, src, 4);
    return r;
}
__device__ __forceinline__ float4 clip4(float4 v) {
    return make_float4(fminf(fmaxf(v.x, -1.f), 1.f),
                       fminf(fmaxf(v.y, -1.f), 1.f),
                       fminf(fmaxf(v.z, -1.f), 1.f),
                       fminf(fmaxf(v.w, -1.f), 1.f));
}
__device__ __forceinline__ float4 neg4(float4 v) {
    return make_float4(-v.x, -v.y, -v.z, -v.w);
}

// fp16 pack/unpack for P rows
__device__ __forceinline__ uint2 pack_h4(float4 v) {
    __half2 lo = __floats2half2_rn(v.x, v.y);
    __half2 hi = __floats2half2_rn(v.z, v.w);
    uint2 u;
    u.x = *reinterpret_cast<unsigned int*>(&lo);
    u.y = *reinterpret_cast<unsigned int*>(&hi);
    return u;
}
__device__ __forceinline__ float4 unpack_h4(uint2 u) {
    __half2 lo = *reinterpret_cast<__half2*>(&u.x);
    __half2 hi = *reinterpret_cast<__half2*>(&u.y);
    float2 a = __half22float2(lo);
    float2 b = __half22float2(hi);
    return make_float4(a.x, a.y, b.x, b.y);
}

// ---------------------------------------------------------------------------
// Kernel 1 (quad-per-edge, shuffle-shared): thread (e, a) loads only row a of
// M1 and M2; other rows via quad shuffles.
//   C1 = M1^T M1 -> atomicAdd diag[row];  C2 = M2^T M2 -> atomicAdd diag[col]
//   P  = M1^T M2 -> fp16-packed streaming store g_triu[e] row a
// ---------------------------------------------------------------------------
__global__ void k_edges(const float* __restrict__ maps,
                        const int*   __restrict__ ei0,
                        int E) {
    int t = blockIdx.x * blockDim.x + threadIdx.x;
    int e = t >> 2, a = t & 3;
    if (e >= E) return;

    const float4* mp = reinterpret_cast<const float4*>(maps);
    float4 m1row = __ldcs(mp + (size_t)e * 4 + a);
    float4 m2row = __ldcs(mp + ((size_t)E + e) * 4 + a);

    float4 c1 = make_float4(0.f, 0.f, 0.f, 0.f);
    float4 c2 = c1, p = c1;
#pragma unroll
    for (int k = 0; k < 4; k++) {
        float4 r1 = shfl4(m1row, k);     // M1 row k
        float4 r2 = shfl4(m2row, k);     // M2 row k
        float s1 = pick(r1, a);          // M1[k][a]
        float s2 = pick(r2, a);          // M2[k][a]
        c1 = f4_fma(s1, r1, c1);
        c2 = f4_fma(s2, r2, c2);
        p  = f4_fma(s1, r2, p);
    }

    int r = ei0[e];
    int c = ei0[E + e];

    atomicAdd(reinterpret_cast<float4*>(g_diag) + (size_t)r * 4 + a, c1);
    atomicAdd(reinterpret_cast<float4*>(g_diag) + (size_t)c * 4 + a, c2);
    __stcs(g_triu + (size_t)e * 4 + a, pack_h4(p));
}

// 4x4 matmul helper (row-major [16])
__device__ __forceinline__ void mm4(const float* __restrict__ A,
                                    const float* __restrict__ B,
                                    float* __restrict__ C) {
#pragma unroll
    for (int i = 0; i < 4; i++) {
#pragma unroll
        for (int j = 0; j < 4; j++) {
            float s = A[i * 4 + 0] * B[0 * 4 + j];
            s += A[i * 4 + 1] * B[1 * 4 + j];
            s += A[i * 4 + 2] * B[2 * 4 + j];
            s += A[i * 4 + 3] * B[3 * 4 + j];
            C[i * 4 + j] = s;
        }
    }
}

// ---------------------------------------------------------------------------
// Kernel 2 (scalar per-node): Z = (diag+I)^{-1/2} via 10 Newton-Schulz
// iterations; store Z, emit diag output block.
// Triggers programmatic launch of k_emit IMMEDIATELY so k_emit's phase 1
// (idx stores, no g_invs dependency) overlaps this kernel's register compute.
// ---------------------------------------------------------------------------
__global__ void k_nodes(float* __restrict__ out, int N, long long L) {
    // Early PDL trigger: k_emit's phase-2 correctness is guaranteed by its own
    // cudaGridDependencySynchronize(); releasing the launch now lets its
    // phase-1 stores fill the DRAM idle under our compute.
    cudaTriggerProgrammaticLaunchCompletion();

    int n = blockIdx.x * blockDim.x + threadIdx.x;
    if (n >= N) return;

    float A0[16], A[16];
    const float4* dp = reinterpret_cast<const float4*>(&g_diag[(size_t)n * 16]);
#pragma unroll
    for (int q = 0; q < 4; q++) {
        float4 v = dp[q];
        A0[q * 4 + 0] = v.x; A0[q * 4 + 1] = v.y; A0[q * 4 + 2] = v.z; A0[q * 4 + 3] = v.w;
    }
#pragma unroll
    for (int i = 0; i < 16; i++) A[i] = A0[i];
    A[0] += 1.f; A[5] += 1.f; A[10] += 1.f; A[15] += 1.f;

    float tr = A[0] + A[5] + A[10] + A[15];
    float g = 0.f;
#pragma unroll
    for (int i = 0; i < 4; i++) {
        float rs = fabsf(A[i * 4 + 0]) + fabsf(A[i * 4 + 1]) +
                   fabsf(A[i * 4 + 2]) + fabsf(A[i * 4 + 3]);
        g = fmaxf(g, rs);
    }
    float s = fminf(tr, g);
    float inv_s = 1.f / s;

    float Y[16], Z[16];
#pragma unroll
    for (int i = 0; i < 16; i++) { Y[i] = A[i] * inv_s; Z[i] = 0.f; }
    Z[0] = Z[5] = Z[10] = Z[15] = 1.f;

#pragma unroll
    for (int it = 0; it < 10; it++) {
        float T[16], Yn[16], Zn[16];
        mm4(Z, Y, T);
#pragma unroll
        for (int i = 0; i < 16; i++) T[i] = -0.5f * T[i];
        T[0] += 1.5f; T[5] += 1.5f; T[10] += 1.5f; T[15] += 1.5f;
        mm4(Y, T, Yn);
        mm4(T, Z, Zn);
#pragma unroll
        for (int i = 0; i < 16; i++) { Y[i] = Yn[i]; Z[i] = Zn[i]; }
    }

    float rs = rsqrtf(s);
#pragma unroll
    for (int i = 0; i < 16; i++) Z[i] *= rs;

    float4* zp = reinterpret_cast<float4*>(&g_invs[(size_t)n * 16]);
#pragma unroll
    for (int q = 0; q < 4; q++)
        zp[q] = *reinterpret_cast<float4*>(&Z[q * 4]);

    float W[16], Dm[16];
    mm4(Z, A0, W);
    mm4(W, Z, Dm);
#pragma unroll
    for (int i = 0; i < 16; i++) Dm[i] = fminf(fmaxf(Dm[i], -1.f), 1.f);

    size_t base = (size_t)n * 16;
    float4* orow = reinterpret_cast<float4*>(out + base);
    float4* ocol = reinterpret_cast<float4*>(out + (size_t)L + base);
    float4* oval = reinterpret_cast<float4*>(out + 2 * (size_t)L + base);
    float nb = (float)(n * 4);
    float4 cv = make_float4(nb, nb + 1.f, nb + 2.f, nb + 3.f);
#pragma unroll
    for (int a = 0; a < 4; a++) {
        float rv = nb + (float)a;
        __stcs(orow + a, make_float4(rv, rv, rv, rv));
        __stcs(ocol + a, cv);
        __stcs(oval + a, *reinterpret_cast<float4*>(&Dm[a * 4]));
    }
}

// ---------------------------------------------------------------------------
// Kernel 3 (PDL two-phase emit, 2 edges per thread):
//   Phase 1 (no g_invs dependency): load r/c/P, emit rows+cols float4s.
//   cudaGridDependencySynchronize() — waits for k_nodes completion.
//   Phase 2: load Zi/Zj, compute T = clip(Zi*P*Zj), emit vals.
// ---------------------------------------------------------------------------
__global__ void k_emit(float* __restrict__ out,
                       const int* __restrict__ ei0,
                       int E, int N, long long L, int hE) {
    int t = blockIdx.x * blockDim.x + threadIdx.x;
    int q = t >> 2, a = t & 3;

    float4* o = reinterpret_cast<float4*>(out);
    size_t L4 = (size_t)L >> 2;

    int e1 = q;
    int e2 = q + hE;
    bool v1 = (q < hE);
    bool v2 = v1 && (e2 < E);

    int r1 = 0, c1 = 0, r2 = 0, c2 = 0;
    float4 Pa1 = make_float4(0.f, 0.f, 0.f, 0.f), Pa2 = Pa1;

    // ---- Phase 1: depends only on edge_index and g_triu (k_edges output) ----
    if (v1) {
        r1 = ei0[e1];
        c1 = ei0[E + e1];
        Pa1 = unpack_h4(__ldcs(g_triu + (size_t)e1 * 4 + a));

        size_t ij = (size_t)N * 4 + (size_t)e1 * 4 + a;
        size_t ji = ij + (size_t)E * 4;
        float rb = (float)(r1 * 4), cb = (float)(c1 * 4);
        float ra = rb + (float)a, ca = cb + (float)a;
        __stcs(o + ij,      make_float4(ra, ra, ra, ra));
        __stcs(o + L4 + ij, make_float4(cb, cb + 1.f, cb + 2.f, cb + 3.f));
        __stcs(o + ji,      make_float4(ca, ca, ca, ca));
        __stcs(o + L4 + ji, make_float4(rb, rb + 1.f, rb + 2.f, rb + 3.f));
    }
    if (v2) {
        r2 = ei0[e2];
        c2 = ei0[E + e2];
        Pa2 = unpack_h4(__ldcs(g_triu + (size_t)e2 * 4 + a));

        size_t ij = (size_t)N * 4 + (size_t)e2 * 4 + a;
        size_t ji = ij + (size_t)E * 4;
        float rb = (float)(r2 * 4), cb = (float)(c2 * 4);
        float ra = rb + (float)a, ca = cb + (float)a;
        __stcs(o + ij,      make_float4(ra, ra, ra, ra));
        __stcs(o + L4 + ij, make_float4(cb, cb + 1.f, cb + 2.f, cb + 3.f));
        __stcs(o + ji,      make_float4(ca, ca, ca, ca));
        __stcs(o + L4 + ji, make_float4(rb, rb + 1.f, rb + 2.f, rb + 3.f));
    }

    // ---- Wait for k_nodes (g_invs producer) ----
    cudaGridDependencySynchronize();

    // ---- Phase 2: sandwich products and vals emission ----
#pragma unroll
    for (int half = 0; half < 2; half++) {
        bool v = half ? v2 : v1;
        if (!v) continue;
        int e = half ? e2 : e1;
        int r = half ? r2 : r1;
        int c = half ? c2 : c1;
        float4 Pa = half ? Pa2 : Pa1;

        float4 zia = __ldg(reinterpret_cast<const float4*>(g_invs) + (size_t)r * 4 + a);
        float4 zja = __ldg(reinterpret_cast<const float4*>(g_invs) + (size_t)c * 4 + a);

        float4 w = make_float4(0.f, 0.f, 0.f, 0.f);
        w = f4_fma(zia.x, shfl4(Pa, 0), w);
        w = f4_fma(zia.y, shfl4(Pa, 1), w);
        w = f4_fma(zia.z, shfl4(Pa, 2), w);
        w = f4_fma(zia.w, shfl4(Pa, 3), w);
        float4 trow = make_float4(0.f, 0.f, 0.f, 0.f);
        trow = f4_fma(w.x, shfl4(zja, 0), trow);
        trow = f4_fma(w.y, shfl4(zja, 1), trow);
        trow = f4_fma(w.z, shfl4(zja, 2), trow);
        trow = f4_fma(w.w, shfl4(zja, 3), trow);
        float4 tc = clip4(trow);

        float4 tcol;
        tcol.x = pick(shfl4(tc, 0), a);
        tcol.y = pick(shfl4(tc, 1), a);
        tcol.z = pick(shfl4(tc, 2), a);
        tcol.w = pick(shfl4(tc, 3), a);

        size_t ij = 2 * L4 + (size_t)N * 4 + (size_t)e * 4 + a;
        size_t ji = ij + (size_t)E * 4;
        __stcs(o + ij, neg4(tc));
        __stcs(o + ji, neg4(tcol));
    }
}

// ---------------------------------------------------------------------------
extern "C" void kernel_launch(void* const* d_in, const int* in_sizes, int n_in,
                              void* d_out, int out_size) {
    const float* maps = (const float*)d_in[0];
    const int*   ei   = (const int*)d_in[1];
    float*       out  = (float*)d_out;

    int twoE = in_sizes[0] / 16;           // 2E
    int E    = twoE / 2;
    long long L = (long long)out_size / 3; // entries per index array
    int N = (int)(L / 16 - twoE);

    int qe = E * 4;
    int hE = (E + 1) / 2;
    int qh = hE * 4;

    static void* diagPtr = nullptr;
    if (!diagPtr) cudaGetSymbolAddress(&diagPtr, g_diag);

    cudaMemsetAsync(diagPtr, 0, (size_t)N * 16 * sizeof(float), 0);
    k_edges<<<(qe + 255) / 256, 256>>>(maps, ei, E);
    k_nodes<<<(N + 127) / 128, 128>>>(out, N, L);

    // PDL launch: k_emit launches as soon as k_nodes triggers (at its top);
    // phase 2 is gated by cudaGridDependencySynchronize() inside the kernel.
    cudaLaunchConfig_t cfg = {};
    cfg.gridDim  = dim3((qh + 255) / 256);
    cfg.blockDim = dim3(256);
    cfg.dynamicSmemBytes = 0;
    cfg.stream = 0;
    cudaLaunchAttribute attrs[1];
    attrs[0].id = cudaLaunchAttributeProgrammaticStreamSerialization;
    attrs[0].val.programmaticStreamSerializationAllowed = 1;
    cfg.attrs = attrs;
    cfg.numAttrs = 1;
    cudaLaunchKernelEx(&cfg, k_emit, out, ei, E, N, L, hE);
}

// round 15
// speedup vs baseline: 1.0189x; 1.0189x over previous
#include <cuda_runtime.h>
#include <cuda_fp16.h>
#include <cstdint>

#define MAXN 50000
#define MAXE 800000

// Device scratch (allocation-free rule: __device__ globals).
// g_diag is zero at module load; k_nodes re-zeros each entry after consuming
// it, so every kernel_launch (and every graph replay) starts from zeros
// without a memset on the critical path.
__device__ float g_diag[(size_t)MAXN * 16];   // per-node Gram accumulators
__device__ float g_invs[(size_t)MAXN * 16];   // per-node inverse sqrt matrices
__device__ uint2 g_triu[(size_t)MAXE * 4];    // per-edge M1^T M2, fp16-packed rows

// float4 helpers
__device__ __forceinline__ float4 f4_fma(float s, float4 v, float4 acc) {
    acc.x = fmaf(s, v.x, acc.x); acc.y = fmaf(s, v.y, acc.y);
    acc.z = fmaf(s, v.z, acc.z); acc.w = fmaf(s, v.w, acc.w);
    return acc;
}
__device__ __forceinline__ float pick(float4 v, int a) {
    float r = v.x;
    r = (a == 1) ? v.y : r;
    r = (a == 2) ? v.z : r;
    r = (a == 3) ? v.w : r;
    return r;
}
__device__ __forceinline__ float4 shfl4(float4 v, int src) {
    float4 r;
    r.x = __shfl_sync(0xffffffffu, v.x, src, 4);
    r.y = __shfl_sync(0xffffffffu, v.y, src, 4);
    r.z = __shfl_sync(0xffffffffu, v.z, src, 4);
    r.w = __shfl_sync(0xffffffffu, v.w, src, 4);
    return r;
}
__device__ __forceinline__ float4 clip4(float4 v) {
    return make_float4(fminf(fmaxf(v.x, -1.f), 1.f),
                       fminf(fmaxf(v.y, -1.f), 1.f),
                       fminf(fmaxf(v.z, -1.f), 1.f),
                       fminf(fmaxf(v.w, -1.f), 1.f));
}
__device__ __forceinline__ float4 neg4(float4 v) {
    return make_float4(-v.x, -v.y, -v.z, -v.w);
}

// fp16 pack/unpack for P rows
__device__ __forceinline__ uint2 pack_h4(float4 v) {
    __half2 lo = __floats2half2_rn(v.x, v.y);
    __half2 hi = __floats2half2_rn(v.z, v.w);
    uint2 u;
    u.x = *reinterpret_cast<unsigned int*>(&lo);
    u.y = *reinterpret_cast<unsigned int*>(&hi);
    return u;
}
__device__ __forceinline__ float4 unpack_h4(uint2 u) {
    __half2 lo = *reinterpret_cast<__half2*>(&u.x);
    __half2 hi = *reinterpret_cast<__half2*>(&u.y);
    float2 a = __half22float2(lo);
    float2 b = __half22float2(hi);
    return make_float4(a.x, a.y, b.x, b.y);
}

// ---------------------------------------------------------------------------
// Kernel 1 (quad-per-edge, shuffle-shared): thread (e, a) loads only row a of
// M1 and M2; other rows via quad shuffles.
//   C1 = M1^T M1 -> atomicAdd diag[row];  C2 = M2^T M2 -> atomicAdd diag[col]
//   P  = M1^T M2 -> fp16-packed streaming store g_triu[e] row a
// ---------------------------------------------------------------------------
__global__ void k_edges(const float* __restrict__ maps,
                        const int*   __restrict__ ei0,
                        int E) {
    int t = blockIdx.x * blockDim.x + threadIdx.x;
    int e = t >> 2, a = t & 3;
    if (e >= E) return;

    const float4* mp = reinterpret_cast<const float4*>(maps);
    float4 m1row = __ldcs(mp + (size_t)e * 4 + a);
    float4 m2row = __ldcs(mp + ((size_t)E + e) * 4 + a);

    float4 c1 = make_float4(0.f, 0.f, 0.f, 0.f);
    float4 c2 = c1, p = c1;
#pragma unroll
    for (int k = 0; k < 4; k++) {
        float4 r1 = shfl4(m1row, k);     // M1 row k
        float4 r2 = shfl4(m2row, k);     // M2 row k
        float s1 = pick(r1, a);          // M1[k][a]
        float s2 = pick(r2, a);          // M2[k][a]
        c1 = f4_fma(s1, r1, c1);
        c2 = f4_fma(s2, r2, c2);
        p  = f4_fma(s1, r2, p);
    }

    int r = ei0[e];
    int c = ei0[E + e];

    atomicAdd(reinterpret_cast<float4*>(g_diag) + (size_t)r * 4 + a, c1);
    atomicAdd(reinterpret_cast<float4*>(g_diag) + (size_t)c * 4 + a, c2);
    __stcs(g_triu + (size_t)e * 4 + a, pack_h4(p));
}

// 4x4 matmul helper (row-major [16])
__device__ __forceinline__ void mm4(const float* __restrict__ A,
                                    const float* __restrict__ B,
                                    float* __restrict__ C) {
#pragma unroll
    for (int i = 0; i < 4; i++) {
#pragma unroll
        for (int j = 0; j < 4; j++) {
            float s = A[i * 4 + 0] * B[0 * 4 + j];
            s += A[i * 4 + 1] * B[1 * 4 + j];
            s += A[i * 4 + 2] * B[2 * 4 + j];
            s += A[i * 4 + 3] * B[3 * 4 + j];
            C[i * 4 + j] = s;
        }
    }
}

// ---------------------------------------------------------------------------
// Kernel 2 (scalar per-node): Z = (diag+I)^{-1/2} via 10 Newton-Schulz
// iterations; store Z, emit diag output block. After consuming g_diag[n],
// re-zeros it so the next graph replay starts from zeros (replaces memset).
// ---------------------------------------------------------------------------
__global__ void k_nodes(float* __restrict__ out, int N, long long L) {
    int n = blockIdx.x * blockDim.x + threadIdx.x;
    if (n >= N) return;

    float A0[16], A[16];
    float4* dp = reinterpret_cast<float4*>(&g_diag[(size_t)n * 16]);
#pragma unroll
    for (int q = 0; q < 4; q++) {
        float4 v = dp[q];
        A0[q * 4 + 0] = v.x; A0[q * 4 + 1] = v.y; A0[q * 4 + 2] = v.z; A0[q * 4 + 3] = v.w;
    }
    // restore the zero invariant for the next replay
    float4 z4 = make_float4(0.f, 0.f, 0.f, 0.f);
#pragma unroll
    for (int q = 0; q < 4; q++) dp[q] = z4;

#pragma unroll
    for (int i = 0; i < 16; i++) A[i] = A0[i];
    A[0] += 1.f; A[5] += 1.f; A[10] += 1.f; A[15] += 1.f;

    float tr = A[0] + A[5] + A[10] + A[15];
    float g = 0.f;
#pragma unroll
    for (int i = 0; i < 4; i++) {
        float rs = fabsf(A[i * 4 + 0]) + fabsf(A[i * 4 + 1]) +
                   fabsf(A[i * 4 + 2]) + fabsf(A[i * 4 + 3]);
        g = fmaxf(g, rs);
    }
    float s = fminf(tr, g);
    float inv_s = 1.f / s;

    float Y[16], Z[16];
#pragma unroll
    for (int i = 0; i < 16; i++) { Y[i] = A[i] * inv_s; Z[i] = 0.f; }
    Z[0] = Z[5] = Z[10] = Z[15] = 1.f;

#pragma unroll
    for (int it = 0; it < 10; it++) {
        float T[16], Yn[16], Zn[16];
        mm4(Z, Y, T);
#pragma unroll
        for (int i = 0; i < 16; i++) T[i] = -0.5f * T[i];
        T[0] += 1.5f; T[5] += 1.5f; T[10] += 1.5f; T[15] += 1.5f;
        mm4(Y, T, Yn);
        mm4(T, Z, Zn);
#pragma unroll
        for (int i = 0; i < 16; i++) { Y[i] = Yn[i]; Z[i] = Zn[i]; }
    }

    float rs = rsqrtf(s);
#pragma unroll
    for (int i = 0; i < 16; i++) Z[i] *= rs;

    float4* zp = reinterpret_cast<float4*>(&g_invs[(size_t)n * 16]);
#pragma unroll
    for (int q = 0; q < 4; q++)
        zp[q] = *reinterpret_cast<float4*>(&Z[q * 4]);

    float W[16], Dm[16];
    mm4(Z, A0, W);
    mm4(W, Z, Dm);
#pragma unroll
    for (int i = 0; i < 16; i++) Dm[i] = fminf(fmaxf(Dm[i], -1.f), 1.f);

    size_t base = (size_t)n * 16;
    float4* orow = reinterpret_cast<float4*>(out + base);
    float4* ocol = reinterpret_cast<float4*>(out + (size_t)L + base);
    float4* oval = reinterpret_cast<float4*>(out + 2 * (size_t)L + base);
    float nb = (float)(n * 4);
    float4 cv = make_float4(nb, nb + 1.f, nb + 2.f, nb + 3.f);
#pragma unroll
    for (int a = 0; a < 4; a++) {
        float rv = nb + (float)a;
        __stcs(orow + a, make_float4(rv, rv, rv, rv));
        __stcs(ocol + a, cv);
        __stcs(oval + a, *reinterpret_cast<float4*>(&Dm[a * 4]));
    }
}

// ---------------------------------------------------------------------------
// Kernel 3 (PDL two-phase emit, 2 edges per thread):
//   Phase 1 (no g_invs dependency): load r/c/P, emit rows+cols float4s.
//   cudaGridDependencySynchronize() — waits for k_nodes completion.
//   Phase 2: load Zi/Zj, compute T = clip(Zi*P*Zj), emit vals.
// ---------------------------------------------------------------------------
__global__ void k_emit(float* __restrict__ out,
                       const int* __restrict__ ei0,
                       int E, int N, long long L, int hE) {
    int t = blockIdx.x * blockDim.x + threadIdx.x;
    int q = t >> 2, a = t & 3;

    float4* o = reinterpret_cast<float4*>(out);
    size_t L4 = (size_t)L >> 2;

    int e1 = q;
    int e2 = q + hE;
    bool v1 = (q < hE);
    bool v2 = v1 && (e2 < E);

    int r1 = 0, c1 = 0, r2 = 0, c2 = 0;
    float4 Pa1 = make_float4(0.f, 0.f, 0.f, 0.f), Pa2 = Pa1;

    // ---- Phase 1: depends only on edge_index and g_triu (k_edges output) ----
    if (v1) {
        r1 = ei0[e1];
        c1 = ei0[E + e1];
        Pa1 = unpack_h4(__ldcs(g_triu + (size_t)e1 * 4 + a));

        size_t ij = (size_t)N * 4 + (size_t)e1 * 4 + a;
        size_t ji = ij + (size_t)E * 4;
        float rb = (float)(r1 * 4), cb = (float)(c1 * 4);
        float ra = rb + (float)a, ca = cb + (float)a;
        __stcs(o + ij,      make_float4(ra, ra, ra, ra));
        __stcs(o + L4 + ij, make_float4(cb, cb + 1.f, cb + 2.f, cb + 3.f));
        __stcs(o + ji,      make_float4(ca, ca, ca, ca));
        __stcs(o + L4 + ji, make_float4(rb, rb + 1.f, rb + 2.f, rb + 3.f));
    }
    if (v2) {
        r2 = ei0[e2];
        c2 = ei0[E + e2];
        Pa2 = unpack_h4(__ldcs(g_triu + (size_t)e2 * 4 + a));

        size_t ij = (size_t)N * 4 + (size_t)e2 * 4 + a;
        size_t ji = ij + (size_t)E * 4;
        float rb = (float)(r2 * 4), cb = (float)(c2 * 4);
        float ra = rb + (float)a, ca = cb + (float)a;
        __stcs(o + ij,      make_float4(ra, ra, ra, ra));
        __stcs(o + L4 + ij, make_float4(cb, cb + 1.f, cb + 2.f, cb + 3.f));
        __stcs(o + ji,      make_float4(ca, ca, ca, ca));
        __stcs(o + L4 + ji, make_float4(rb, rb + 1.f, rb + 2.f, rb + 3.f));
    }

    // ---- Wait for k_nodes (g_invs producer) ----
    cudaGridDependencySynchronize();

    // ---- Phase 2: sandwich products and vals emission ----
#pragma unroll
    for (int half = 0; half < 2; half++) {
        bool v = half ? v2 : v1;
        if (!v) continue;
        int e = half ? e2 : e1;
        int r = half ? r2 : r1;
        int c = half ? c2 : c1;
        float4 Pa = half ? Pa2 : Pa1;

        float4 zia = __ldg(reinterpret_cast<const float4*>(g_invs) + (size_t)r * 4 + a);
        float4 zja = __ldg(reinterpret_cast<const float4*>(g_invs) + (size_t)c * 4 + a);

        float4 w = make_float4(0.f, 0.f, 0.f, 0.f);
        w = f4_fma(zia.x, shfl4(Pa, 0), w);
        w = f4_fma(zia.y, shfl4(Pa, 1), w);
        w = f4_fma(zia.z, shfl4(Pa, 2), w);
        w = f4_fma(zia.w, shfl4(Pa, 3), w);
        float4 trow = make_float4(0.f, 0.f, 0.f, 0.f);
        trow = f4_fma(w.x, shfl4(zja, 0), trow);
        trow = f4_fma(w.y, shfl4(zja, 1), trow);
        trow = f4_fma(w.z, shfl4(zja, 2), trow);
        trow = f4_fma(w.w, shfl4(zja, 3), trow);
        float4 tc = clip4(trow);

        float4 tcol;
        tcol.x = pick(shfl4(tc, 0), a);
        tcol.y = pick(shfl4(tc, 1), a);
        tcol.z = pick(shfl4(tc, 2), a);
        tcol.w = pick(shfl4(tc, 3), a);

        size_t ij = 2 * L4 + (size_t)N * 4 + (size_t)e * 4 + a;
        size_t ji = ij + (size_t)E * 4;
        __stcs(o + ij, neg4(tc));
        __stcs(o + ji, neg4(tcol));
    }
}

// ---------------------------------------------------------------------------
extern "C" void kernel_launch(void* const* d_in, const int* in_sizes, int n_in,
                              void* d_out, int out_size) {
    const float* maps = (const float*)d_in[0];
    const int*   ei   = (const int*)d_in[1];
    float*       out  = (float*)d_out;

    int twoE = in_sizes[0] / 16;           // 2E
    int E    = twoE / 2;
    long long L = (long long)out_size / 3; // entries per index array
    int N = (int)(L / 16 - twoE);

    int qe = E * 4;
    int hE = (E + 1) / 2;
    int qh = hE * 4;

    k_edges<<<(qe + 255) / 256, 256>>>(maps, ei, E);
    k_nodes<<<(N + 127) / 128, 128>>>(out, N, L);

    // PDL launch: k_emit's phase 2 is gated by cudaGridDependencySynchronize()
    // inside the kernel (implicit trigger at k_nodes completion).
    cudaLaunchConfig_t cfg = {};
    cfg.gridDim  = dim3((qh + 255) / 256);
    cfg.blockDim = dim3(256);
    cfg.dynamicSmemBytes = 0;
    cfg.stream = 0;
    cudaLaunchAttribute attrs[1];
    attrs[0].id = cudaLaunchAttributeProgrammaticStreamSerialization;
    attrs[0].val.programmaticStreamSerializationAllowed = 1;
    cfg.attrs = attrs;
    cfg.numAttrs = 1;
    cudaLaunchKernelEx(&cfg, k_emit, out, ei, E, N, L, hE);
}